// round 15
// baseline (speedup 1.0000x reference)
#include <cuda_runtime.h>
#include <cuda_bf16.h>
#include <math.h>
#include <stdint.h>

#define T_LEN 4096
#define DIM 768
#define HEADS 12
#define HD 64
#define RMS_EPS 1.1920928955078125e-07f
#define ATTN_SCALE 0.12f

__device__ float g_qkv[T_LEN * 3 * DIM];
__device__ float g_Y [T_LEN * DIM];
__device__ __nv_bfloat16 g_Qh[HEADS * T_LEN * HD];
__device__ __nv_bfloat16 g_Ql[HEADS * T_LEN * HD];
__device__ __nv_bfloat16 g_Kh[HEADS * T_LEN * HD];
__device__ __nv_bfloat16 g_Kl[HEADS * T_LEN * HD];
__device__ __nv_bfloat16 g_Vh[HEADS * T_LEN * HD];
__device__ __nv_bfloat16 g_Vl[HEADS * T_LEN * HD];

// ---------------- mma.sync (base-ISA HMMA) ----------------
__device__ __forceinline__ void mma16816(float* c, const uint32_t* a, const uint32_t* b) {
    asm volatile(
        "mma.sync.aligned.m16n8k16.row.col.f32.bf16.bf16.f32 "
        "{%0,%1,%2,%3}, {%4,%5,%6,%7}, {%8,%9}, {%0,%1,%2,%3};"
        : "+f"(c[0]), "+f"(c[1]), "+f"(c[2]), "+f"(c[3])
        : "r"(a[0]), "r"(a[1]), "r"(a[2]), "r"(a[3]), "r"(b[0]), "r"(b[1]));
}

__device__ __forceinline__ void split2(float x, float y, uint32_t& hi, uint32_t& lo) {
    __nv_bfloat162 h;
    h.x = __float2bfloat16_rn(x);
    h.y = __float2bfloat16_rn(y);
    __nv_bfloat162 l = __floats2bfloat162_rn(x - __bfloat162float(h.x),
                                             y - __bfloat162float(h.y));
    hi = *reinterpret_cast<uint32_t*>(&h);
    lo = *reinterpret_cast<uint32_t*>(&l);
}

// ---------------- no-op pad kernels (shift ncu capture slot onto flash) ----------------
__global__ void nop_kernel() {}

// ================= dense GEMM (unchanged, proven) =================
__global__ __launch_bounds__(256, 1) void gemm_mma(const float* __restrict__ A,
                                                   const float* __restrict__ B,
                                                   float* __restrict__ C,
                                                   int M, int N, int K) {
    __shared__ __align__(16) uint8_t sAh[8192];
    __shared__ __align__(16) uint8_t sAl[8192];
    __shared__ __align__(16) uint8_t sBh[8192];
    __shared__ __align__(16) uint8_t sBl[8192];

    const int tid = threadIdx.x;
    const int wid = tid >> 5;
    const int lane = tid & 31;
    const int row0 = blockIdx.y * 128;
    const int col0 = blockIdx.x * 128;

    const int prow = tid >> 1;
    const int hf = tid & 1;
    const float* Ar = A + (size_t)(row0 + prow) * K;
    const float* Br = B + (size_t)(col0 + prow) * K;

    const int mt = prow >> 4, rr = prow & 15;
    const int ar = rr & 7, up = rr >> 3;
    const int aBase = ((mt * 2 + hf) * 32) * 16;
    const int nt = prow >> 3, nn = prow & 7;
    const int bBase = ((nt * 2 + hf) * 32) * 8;

    float acc[4][4][4];
#pragma unroll
    for (int i = 0; i < 4; i++)
#pragma unroll
        for (int j = 0; j < 4; j++)
#pragma unroll
            for (int k = 0; k < 4; k++) acc[i][j][k] = 0.f;

    const int nch = K >> 5;
    float4 ra[4], rb[4];
#pragma unroll
    for (int i = 0; i < 4; i++) {
        int kc = hf * 16 + i * 4;
        ra[i] = *(const float4*)&Ar[kc];
        rb[i] = *(const float4*)&Br[kc];
    }

    const int wm = (wid & 1) * 4;
    const int wn = (wid >> 1) * 4;

    for (int ch = 0; ch < nch; ch++) {
#pragma unroll
        for (int i = 0; i < 4; i++) {
            int la = aBase + (ar * 4 + (i & 1) * 2) * 16 + up * 4 + (i >> 1) * 8;
            uint32_t hi0, lo0, hi1, lo1;
            split2(ra[i].x, ra[i].y, hi0, lo0);
            split2(ra[i].z, ra[i].w, hi1, lo1);
            *(uint32_t*)(sAh + la) = hi0;
            *(uint32_t*)(sAl + la) = lo0;
            *(uint32_t*)(sAh + la + 16) = hi1;
            *(uint32_t*)(sAl + la + 16) = lo1;
            int lb = bBase + (nn * 4 + (i & 1) * 2) * 8 + (i >> 1) * 4;
            split2(rb[i].x, rb[i].y, hi0, lo0);
            split2(rb[i].z, rb[i].w, hi1, lo1);
            *(uint32_t*)(sBh + lb) = hi0;
            *(uint32_t*)(sBl + lb) = lo0;
            *(uint32_t*)(sBh + lb + 8) = hi1;
            *(uint32_t*)(sBl + lb + 8) = lo1;
        }
        if (ch + 1 < nch) {
            int cb = (ch + 1) * 32 + hf * 16;
#pragma unroll
            for (int i = 0; i < 4; i++) {
                ra[i] = *(const float4*)&Ar[cb + i * 4];
                rb[i] = *(const float4*)&Br[cb + i * 4];
            }
        }
        __syncthreads();

#pragma unroll
        for (int s = 0; s < 2; s++) {
            uint4 ah[4], al[4];
            uint2 bh[4], bl[4];
#pragma unroll
            for (int i = 0; i < 4; i++) {
                int off = (((wm + i) * 2 + s) * 32 + lane) * 16;
                ah[i] = *(const uint4*)(sAh + off);
                al[i] = *(const uint4*)(sAl + off);
            }
#pragma unroll
            for (int j = 0; j < 4; j++) {
                int off = (((wn + j) * 2 + s) * 32 + lane) * 8;
                bh[j] = *(const uint2*)(sBh + off);
                bl[j] = *(const uint2*)(sBl + off);
            }
#pragma unroll
            for (int i = 0; i < 4; i++)
#pragma unroll
                for (int j = 0; j < 4; j++) {
                    mma16816(acc[i][j], (uint32_t*)&ah[i], (uint32_t*)&bh[j]);
                    mma16816(acc[i][j], (uint32_t*)&ah[i], (uint32_t*)&bl[j]);
                    mma16816(acc[i][j], (uint32_t*)&al[i], (uint32_t*)&bh[j]);
                }
        }
        __syncthreads();
    }

    const int erow = row0 + (wid & 1) * 64 + (lane >> 2);
    const int ecol = col0 + (wid >> 1) * 32 + (lane & 3) * 2;
#pragma unroll
    for (int i = 0; i < 4; i++)
#pragma unroll
        for (int j = 0; j < 4; j++) {
            float* p0 = &C[(size_t)(erow + i * 16) * N + ecol + j * 8];
            float* p1 = &C[(size_t)(erow + i * 16 + 8) * N + ecol + j * 8];
            *(float2*)p0 = make_float2(acc[i][j][0], acc[i][j][1]);
            *(float2*)p1 = make_float2(acc[i][j][2], acc[i][j][3]);
        }
}

// ---------------- prep: RMS + rotary -> bf16 hi/lo [h][t][d]; Q pre-scaled ----------------
__global__ void prep_kernel(const float* __restrict__ qkv) {
    int gwarp = (blockIdx.x * blockDim.x + threadIdx.x) >> 5;
    int lane = threadIdx.x & 31;
    if (gwarp >= T_LEN * HEADS) return;
    int t = gwarp / HEADS;
    int h = gwarp % HEADS;
    const float* base = qkv + (size_t)t * (3 * DIM) + h * HD;

    float q1 = base[lane],            q2 = base[lane + 32];
    float k1 = base[DIM + lane],      k2 = base[DIM + lane + 32];
    float v1 = base[2 * DIM + lane],  v2 = base[2 * DIM + lane + 32];

    float sq = q1 * q1 + q2 * q2;
    float sk = k1 * k1 + k2 * k2;
#pragma unroll
    for (int o = 16; o > 0; o >>= 1) {
        sq += __shfl_xor_sync(0xffffffffu, sq, o);
        sk += __shfl_xor_sync(0xffffffffu, sk, o);
    }
    float rq = rsqrtf(sq * (1.f / 64.f) + RMS_EPS);
    float rk = rsqrtf(sk * (1.f / 64.f) + RMS_EPS);
    q1 *= rq; q2 *= rq;
    k1 *= rk; k2 *= rk;

    float freq = (lane < 16) ? exp2f((float)lane * (-10.0f / 15.0f)) : 0.0f;
    float theta = (float)t * freq;
    float s, c;
    sincosf(theta, &s, &c);

    // fold ATTN_SCALE into Q (commutes with rotary rotation and the bf16 split)
    float qa = (q1 * c + q2 * s) * ATTN_SCALE;
    float qb = (-q1 * s + q2 * c) * ATTN_SCALE;
    float ka = k1 * c + k2 * s;
    float kb = -k1 * s + k2 * c;

    size_t o0 = ((size_t)h * T_LEN + t) * HD + lane;
    size_t o1 = o0 + 32;
#define SPLIT_ST(arrH, arrL, idx, val) do { \
        __nv_bfloat16 _h = __float2bfloat16_rn(val); \
        arrH[idx] = _h; \
        arrL[idx] = __float2bfloat16_rn((val) - __bfloat162float(_h)); \
    } while (0)
    SPLIT_ST(g_Qh, g_Ql, o0, qa); SPLIT_ST(g_Qh, g_Ql, o1, qb);
    SPLIT_ST(g_Kh, g_Kl, o0, ka); SPLIT_ST(g_Kh, g_Kl, o1, kb);
    SPLIT_ST(g_Vh, g_Vl, o0, v1); SPLIT_ST(g_Vh, g_Vl, o1, v2);
#undef SPLIT_ST
}

// ---------------- flash attention: warp = m32 x n32 (Q pre-scaled) ----------------
__global__ __launch_bounds__(256, 1)
void flash_mma(float* __restrict__ Y) {
    extern __shared__ uint32_t smw[];
    float* smf = (float*)smw;

    const int h = blockIdx.y;
    const int qb = (gridDim.x - 1) - blockIdx.x;
    const int q0 = qb * 128;
    const int tid = threadIdx.x;
    const int w = tid >> 5;
    const int lane = tid & 31;
    const int gid = lane >> 2;
    const int tig = lane & 3;
    const int wm = w & 3;
    const int wn = w >> 2;
    const int rbase = q0 + wm * 32;

    const uint32_t* gQh = (const uint32_t*)g_Qh + ((size_t)h * T_LEN + q0) * 32;
    const uint32_t* gQl = (const uint32_t*)g_Ql + ((size_t)h * T_LEN + q0) * 32;
    const uint32_t* gKh = (const uint32_t*)g_Kh + (size_t)h * T_LEN * 32;
    const uint32_t* gKl = (const uint32_t*)g_Kl + (size_t)h * T_LEN * 32;
    const uint32_t* gVh = (const uint32_t*)g_Vh + (size_t)h * T_LEN * 32;
    const uint32_t* gVl = (const uint32_t*)g_Vl + (size_t)h * T_LEN * 32;

    {
        const int t = tid >> 1;
        const int mt = t >> 4, rr = t & 15;
        const int g8 = rr & 7, wb = rr >> 3;
#pragma unroll
        for (int jj = 0; jj < 2; jj++) {
            int dw0 = (tid & 1) * 16 + jj * 8;
#pragma unroll
            for (int half = 0; half < 2; half++) {
                uint4 qh4 = *(const uint4*)(gQh + (size_t)t * 32 + dw0 + half * 4);
                uint4 ql4 = *(const uint4*)(gQl + (size_t)t * 32 + dw0 + half * 4);
#pragma unroll
                for (int c = 0; c < 4; c++) {
                    int dw = dw0 + half * 4 + c;
                    int s = dw >> 3, tg = dw & 3, hi4 = (dw >> 2) & 1;
                    int addr = ((mt * 4 + s) * 32 + g8 * 4 + tg) * 4 + wb + 2 * hi4;
                    smw[addr] = ((const uint32_t*)&qh4)[c];
                    smw[addr + 4096] = ((const uint32_t*)&ql4)[c];
                }
            }
        }
    }

    const int kt = tid >> 2, kss = tid & 3;
    const int knt = kt >> 3, kg8 = kt & 7;
    const int kdst = 8192 + ((knt * 4 + kss) * 32 + kg8 * 4) * 4;
    const int jp = tid >> 3, dwb = (tid & 7) * 4;
    const int vs = jp >> 3, vqq = jp & 7;
    const int vword = vqq >> 2, vtg = vqq & 3;

    uint4 pk[4], pv[4];
    {
        const uint32_t* sKh = gKh + (size_t)kt * 32 + kss * 8;
        const uint32_t* sKl = gKl + (size_t)kt * 32 + kss * 8;
        pk[0] = *(const uint4*)sKh;       pk[1] = *(const uint4*)(sKh + 4);
        pk[2] = *(const uint4*)sKl;       pk[3] = *(const uint4*)(sKl + 4);
        pv[0] = *(const uint4*)(gVh + (size_t)(2 * jp) * 32 + dwb);
        pv[1] = *(const uint4*)(gVh + (size_t)(2 * jp + 1) * 32 + dwb);
        pv[2] = *(const uint4*)(gVl + (size_t)(2 * jp) * 32 + dwb);
        pv[3] = *(const uint4*)(gVl + (size_t)(2 * jp + 1) * 32 + dwb);
    }

    float O[2][8][4];
#pragma unroll
    for (int a = 0; a < 2; a++)
#pragma unroll
        for (int b = 0; b < 8; b++)
#pragma unroll
            for (int c = 0; c < 4; c++) O[a][b][c] = 0.f;
    float lsum[2][2] = {{0.f, 0.f}, {0.f, 0.f}};

    const int ntiles = 2 * qb + 2;
    for (int it = 0; it < ntiles; it++) {
        const int k0 = it * 64;
        __syncthreads();
#pragma unroll
        for (int c = 0; c < 4; c++) {
            *(uint4*)(smw + kdst + c * 4) =
                make_uint4(((uint32_t*)&pk[0])[c], ((uint32_t*)&pk[1])[c],
                           ((uint32_t*)&pk[2])[c], ((uint32_t*)&pk[3])[c]);
        }
#pragma unroll
        for (int c = 0; c < 4; c++) {
            int d0 = 2 * (dwb + c);
            int nt8 = d0 >> 3, g0 = d0 & 7;
            int slot0 = (nt8 * 4 + vs) * 32 + g0 * 4 + vtg;
            uint32_t w0 = ((uint32_t*)&pv[0])[c], w1 = ((uint32_t*)&pv[1])[c];
            uint32_t u0 = ((uint32_t*)&pv[2])[c], u1 = ((uint32_t*)&pv[3])[c];
            smw[12288 + slot0 * 4 + vword] = __byte_perm(w0, w1, 0x5410);
            smw[12288 + slot0 * 4 + vword + 2] = __byte_perm(u0, u1, 0x5410);
            smw[12288 + (slot0 + 4) * 4 + vword] = __byte_perm(w0, w1, 0x7632);
            smw[12288 + (slot0 + 4) * 4 + vword + 2] = __byte_perm(u0, u1, 0x7632);
        }
        if (it + 1 < ntiles) {
            const int k0n = k0 + 64;
            const uint32_t* sKh = gKh + (size_t)(k0n + kt) * 32 + kss * 8;
            const uint32_t* sKl = gKl + (size_t)(k0n + kt) * 32 + kss * 8;
            pk[0] = *(const uint4*)sKh;   pk[1] = *(const uint4*)(sKh + 4);
            pk[2] = *(const uint4*)sKl;   pk[3] = *(const uint4*)(sKl + 4);
            pv[0] = *(const uint4*)(gVh + (size_t)(k0n + 2 * jp) * 32 + dwb);
            pv[1] = *(const uint4*)(gVh + (size_t)(k0n + 2 * jp + 1) * 32 + dwb);
            pv[2] = *(const uint4*)(gVl + (size_t)(k0n + 2 * jp) * 32 + dwb);
            pv[3] = *(const uint4*)(gVl + (size_t)(k0n + 2 * jp + 1) * 32 + dwb);
        }
        __syncthreads();

        const int k0c = k0 + wn * 32;
        if (k0c > rbase + 31) continue;

        float S[2][4][4];
#pragma unroll
        for (int a = 0; a < 2; a++)
#pragma unroll
            for (int b = 0; b < 4; b++)
#pragma unroll
                for (int c = 0; c < 4; c++) S[a][b][c] = 0.f;
#pragma unroll
        for (int s = 0; s < 4; s++) {
            uint4 ah[2], al[2];
#pragma unroll
            for (int mt = 0; mt < 2; mt++) {
                int slot = (((wm * 2 + mt) * 4 + s) * 32 + lane) * 4;
                ah[mt] = *(const uint4*)(smw + slot);
                al[mt] = *(const uint4*)(smw + slot + 4096);
            }
#pragma unroll
            for (int nt = 0; nt < 4; nt++) {
                uint4 kk = *(const uint4*)(smw + 8192 +
                                           (((wn * 4 + nt) * 4 + s) * 32 + lane) * 4);
                uint32_t bh[2] = {kk.x, kk.y}, bl[2] = {kk.z, kk.w};
#pragma unroll
                for (int mt = 0; mt < 2; mt++) {
                    mma16816(S[mt][nt], (uint32_t*)&ah[mt], bh);
                    mma16816(S[mt][nt], (uint32_t*)&ah[mt], bl);
                    mma16816(S[mt][nt], (uint32_t*)&al[mt], bh);
                }
            }
        }

        const bool needmask = (k0c + 31 > rbase);
#pragma unroll
        for (int mt = 0; mt < 2; mt++) {
            const int r0 = rbase + mt * 16 + gid, r1 = r0 + 8;
#pragma unroll
            for (int nt = 0; nt < 4; nt++) {
                int c0 = k0c + nt * 8 + tig * 2;
                float p0 = __expf(S[mt][nt][0]);
                float p1 = __expf(S[mt][nt][1]);
                float p2 = __expf(S[mt][nt][2]);
                float p3 = __expf(S[mt][nt][3]);
                if (needmask) {
                    if (c0 > r0) p0 = 0.f;
                    if (c0 + 1 > r0) p1 = 0.f;
                    if (c0 > r1) p2 = 0.f;
                    if (c0 + 1 > r1) p3 = 0.f;
                }
                lsum[mt][0] += p0 + p1;
                lsum[mt][1] += p2 + p3;
                S[mt][nt][0] = p0; S[mt][nt][1] = p1;
                S[mt][nt][2] = p2; S[mt][nt][3] = p3;
            }
        }

#pragma unroll
        for (int s2 = 0; s2 < 2; s2++) {
            uint32_t Ph[2][4], Pl[2][4];
#pragma unroll
            for (int mt = 0; mt < 2; mt++) {
                split2(S[mt][2 * s2][0], S[mt][2 * s2][1], Ph[mt][0], Pl[mt][0]);
                split2(S[mt][2 * s2][2], S[mt][2 * s2][3], Ph[mt][1], Pl[mt][1]);
                split2(S[mt][2 * s2 + 1][0], S[mt][2 * s2 + 1][1], Ph[mt][2], Pl[mt][2]);
                split2(S[mt][2 * s2 + 1][2], S[mt][2 * s2 + 1][3], Ph[mt][3], Pl[mt][3]);
            }
#pragma unroll
            for (int nt8 = 0; nt8 < 8; nt8++) {
                uint4 vv = *(const uint4*)(smw + 12288 +
                                           ((nt8 * 4 + wn * 2 + s2) * 32 + lane) * 4);
                uint32_t bh[2] = {vv.x, vv.y}, bl[2] = {vv.z, vv.w};
#pragma unroll
                for (int mt = 0; mt < 2; mt++) {
                    mma16816(O[mt][nt8], Ph[mt], bh);
                    mma16816(O[mt][nt8], Ph[mt], bl);
                    mma16816(O[mt][nt8], Pl[mt], bh);
                }
            }
        }
    }

#pragma unroll
    for (int mt = 0; mt < 2; mt++)
#pragma unroll
        for (int i = 0; i < 2; i++) {
            lsum[mt][i] += __shfl_xor_sync(0xffffffffu, lsum[mt][i], 1, 4);
            lsum[mt][i] += __shfl_xor_sync(0xffffffffu, lsum[mt][i], 2, 4);
        }

    __syncthreads();
    float* ex = smf + wm * 3072;
    if (wn == 1) {
#pragma unroll
        for (int mt = 0; mt < 2; mt++) {
#pragma unroll
            for (int nt8 = 0; nt8 < 8; nt8++) {
                int col = nt8 * 8 + tig * 2;
                *(float2*)&ex[(mt * 16 + gid) * 66 + col] =
                    make_float2(O[mt][nt8][0], O[mt][nt8][1]);
                *(float2*)&ex[(mt * 16 + gid + 8) * 66 + col] =
                    make_float2(O[mt][nt8][2], O[mt][nt8][3]);
            }
            if (tig == 0) {
                ex[(mt * 16 + gid) * 66 + 64] = lsum[mt][0];
                ex[(mt * 16 + gid + 8) * 66 + 64] = lsum[mt][1];
            }
        }
    }
    __syncthreads();
    if (wn == 0) {
#pragma unroll
        for (int mt = 0; mt < 2; mt++) {
            float lt0 = lsum[mt][0] + ex[(mt * 16 + gid) * 66 + 64];
            float lt1 = lsum[mt][1] + ex[(mt * 16 + gid + 8) * 66 + 64];
            float inv0 = 1.f / lt0, inv1 = 1.f / lt1;
            int r0 = rbase + mt * 16 + gid;
#pragma unroll
            for (int nt8 = 0; nt8 < 8; nt8++) {
                int col = nt8 * 8 + tig * 2;
                float2 e0 = *(float2*)&ex[(mt * 16 + gid) * 66 + col];
                float2 e1 = *(float2*)&ex[(mt * 16 + gid + 8) * 66 + col];
                int yc = h * HD + col;
                *(float2*)&Y[(size_t)r0 * DIM + yc] =
                    make_float2((O[mt][nt8][0] + e0.x) * inv0,
                                (O[mt][nt8][1] + e0.y) * inv0);
                *(float2*)&Y[(size_t)(r0 + 8) * DIM + yc] =
                    make_float2((O[mt][nt8][2] + e1.x) * inv1,
                                (O[mt][nt8][3] + e1.y) * inv1);
            }
        }
    }
}

// ---------------- launch ----------------
extern "C" void kernel_launch(void* const* d_in, const int* in_sizes, int n_in,
                              void* d_out, int out_size) {
    const float* x = (const float*)d_in[0];
    const float* qkv_w = (const float*)d_in[1];
    const float* c_proj_w = (const float*)d_in[2];
    float* out = (float*)d_out;

    float *qkv, *Yb;
    cudaGetSymbolAddress((void**)&qkv, g_qkv);
    cudaGetSymbolAddress((void**)&Yb, g_Y);

    // 1) qkv = x @ qkv_w^T
    {
        dim3 grid(2304 / 128, T_LEN / 128);
        gemm_mma<<<grid, 256>>>(x, qkv_w, qkv, T_LEN, 2304, DIM);
    }
    // 2) RMS + rotary -> bf16 hi/lo (Q pre-scaled by ATTN_SCALE)
    {
        int warps = T_LEN * HEADS;
        int blocks = (warps * 32 + 255) / 256;
        prep_kernel<<<blocks, 256>>>(qkv);
    }
    // 3) two no-op pads so ncu's capture slot (global launch idx 4) = flash_mma
    nop_kernel<<<1, 32>>>();
    nop_kernel<<<1, 32>>>();
    // 4) flash attention
    {
        cudaFuncSetAttribute(flash_mma, cudaFuncAttributeMaxDynamicSharedMemorySize, 65536);
        dim3 grid(T_LEN / 128, HEADS);
        flash_mma<<<grid, 256, 65536>>>(Yb);
    }
    // 5) out = Y @ c_proj_w^T
    {
        dim3 grid(DIM / 128, T_LEN / 128);
        gemm_mma<<<grid, 256>>>(Yb, c_proj_w, out, T_LEN, DIM, DIM);
    }
}

// round 16
// speedup vs baseline: 1.0249x; 1.0249x over previous
#include <cuda_runtime.h>
#include <cuda_bf16.h>
#include <math.h>
#include <stdint.h>

#define T_LEN 4096
#define DIM 768
#define HEADS 12
#define HD 64
#define RMS_EPS 1.1920928955078125e-07f
#define ATTN_SCALE 0.12f

__device__ float g_qkv[T_LEN * 3 * DIM];
__device__ float g_Y [T_LEN * DIM];
__device__ __nv_bfloat16 g_Qh[HEADS * T_LEN * HD];
__device__ __nv_bfloat16 g_Ql[HEADS * T_LEN * HD];
__device__ __nv_bfloat16 g_Kh[HEADS * T_LEN * HD];
__device__ __nv_bfloat16 g_Kl[HEADS * T_LEN * HD];
__device__ __nv_bfloat16 g_Vh[HEADS * T_LEN * HD];
__device__ __nv_bfloat16 g_Vl[HEADS * T_LEN * HD];

// ---------------- mma.sync (base-ISA HMMA) ----------------
__device__ __forceinline__ void mma16816(float* c, const uint32_t* a, const uint32_t* b) {
    asm volatile(
        "mma.sync.aligned.m16n8k16.row.col.f32.bf16.bf16.f32 "
        "{%0,%1,%2,%3}, {%4,%5,%6,%7}, {%8,%9}, {%0,%1,%2,%3};"
        : "+f"(c[0]), "+f"(c[1]), "+f"(c[2]), "+f"(c[3])
        : "r"(a[0]), "r"(a[1]), "r"(a[2]), "r"(a[3]), "r"(b[0]), "r"(b[1]));
}

__device__ __forceinline__ void split2(float x, float y, uint32_t& hi, uint32_t& lo) {
    __nv_bfloat162 h;
    h.x = __float2bfloat16_rn(x);
    h.y = __float2bfloat16_rn(y);
    __nv_bfloat162 l = __floats2bfloat162_rn(x - __bfloat162float(h.x),
                                             y - __bfloat162float(h.y));
    hi = *reinterpret_cast<uint32_t*>(&h);
    lo = *reinterpret_cast<uint32_t*>(&l);
}

__global__ void nop_kernel() {}

// ================= dense GEMM (unchanged, proven) =================
__global__ __launch_bounds__(256, 1) void gemm_mma(const float* __restrict__ A,
                                                   const float* __restrict__ B,
                                                   float* __restrict__ C,
                                                   int M, int N, int K) {
    __shared__ __align__(16) uint8_t sAh[8192];
    __shared__ __align__(16) uint8_t sAl[8192];
    __shared__ __align__(16) uint8_t sBh[8192];
    __shared__ __align__(16) uint8_t sBl[8192];

    const int tid = threadIdx.x;
    const int wid = tid >> 5;
    const int lane = tid & 31;
    const int row0 = blockIdx.y * 128;
    const int col0 = blockIdx.x * 128;

    const int prow = tid >> 1;
    const int hf = tid & 1;
    const float* Ar = A + (size_t)(row0 + prow) * K;
    const float* Br = B + (size_t)(col0 + prow) * K;

    const int mt = prow >> 4, rr = prow & 15;
    const int ar = rr & 7, up = rr >> 3;
    const int aBase = ((mt * 2 + hf) * 32) * 16;
    const int nt = prow >> 3, nn = prow & 7;
    const int bBase = ((nt * 2 + hf) * 32) * 8;

    float acc[4][4][4];
#pragma unroll
    for (int i = 0; i < 4; i++)
#pragma unroll
        for (int j = 0; j < 4; j++)
#pragma unroll
            for (int k = 0; k < 4; k++) acc[i][j][k] = 0.f;

    const int nch = K >> 5;
    float4 ra[4], rb[4];
#pragma unroll
    for (int i = 0; i < 4; i++) {
        int kc = hf * 16 + i * 4;
        ra[i] = *(const float4*)&Ar[kc];
        rb[i] = *(const float4*)&Br[kc];
    }

    const int wm = (wid & 1) * 4;
    const int wn = (wid >> 1) * 4;

    for (int ch = 0; ch < nch; ch++) {
#pragma unroll
        for (int i = 0; i < 4; i++) {
            int la = aBase + (ar * 4 + (i & 1) * 2) * 16 + up * 4 + (i >> 1) * 8;
            uint32_t hi0, lo0, hi1, lo1;
            split2(ra[i].x, ra[i].y, hi0, lo0);
            split2(ra[i].z, ra[i].w, hi1, lo1);
            *(uint32_t*)(sAh + la) = hi0;
            *(uint32_t*)(sAl + la) = lo0;
            *(uint32_t*)(sAh + la + 16) = hi1;
            *(uint32_t*)(sAl + la + 16) = lo1;
            int lb = bBase + (nn * 4 + (i & 1) * 2) * 8 + (i >> 1) * 4;
            split2(rb[i].x, rb[i].y, hi0, lo0);
            split2(rb[i].z, rb[i].w, hi1, lo1);
            *(uint32_t*)(sBh + lb) = hi0;
            *(uint32_t*)(sBl + lb) = lo0;
            *(uint32_t*)(sBh + lb + 8) = hi1;
            *(uint32_t*)(sBl + lb + 8) = lo1;
        }
        if (ch + 1 < nch) {
            int cb = (ch + 1) * 32 + hf * 16;
#pragma unroll
            for (int i = 0; i < 4; i++) {
                ra[i] = *(const float4*)&Ar[cb + i * 4];
                rb[i] = *(const float4*)&Br[cb + i * 4];
            }
        }
        __syncthreads();

#pragma unroll
        for (int s = 0; s < 2; s++) {
            uint4 ah[4], al[4];
            uint2 bh[4], bl[4];
#pragma unroll
            for (int i = 0; i < 4; i++) {
                int off = (((wm + i) * 2 + s) * 32 + lane) * 16;
                ah[i] = *(const uint4*)(sAh + off);
                al[i] = *(const uint4*)(sAl + off);
            }
#pragma unroll
            for (int j = 0; j < 4; j++) {
                int off = (((wn + j) * 2 + s) * 32 + lane) * 8;
                bh[j] = *(const uint2*)(sBh + off);
                bl[j] = *(const uint2*)(sBl + off);
            }
#pragma unroll
            for (int i = 0; i < 4; i++)
#pragma unroll
                for (int j = 0; j < 4; j++) {
                    mma16816(acc[i][j], (uint32_t*)&ah[i], (uint32_t*)&bh[j]);
                    mma16816(acc[i][j], (uint32_t*)&ah[i], (uint32_t*)&bl[j]);
                    mma16816(acc[i][j], (uint32_t*)&al[i], (uint32_t*)&bh[j]);
                }
        }
        __syncthreads();
    }

    const int erow = row0 + (wid & 1) * 64 + (lane >> 2);
    const int ecol = col0 + (wid >> 1) * 32 + (lane & 3) * 2;
#pragma unroll
    for (int i = 0; i < 4; i++)
#pragma unroll
        for (int j = 0; j < 4; j++) {
            float* p0 = &C[(size_t)(erow + i * 16) * N + ecol + j * 8];
            float* p1 = &C[(size_t)(erow + i * 16 + 8) * N + ecol + j * 8];
            *(float2*)p0 = make_float2(acc[i][j][0], acc[i][j][1]);
            *(float2*)p1 = make_float2(acc[i][j][2], acc[i][j][3]);
        }
}

// ---------------- prep: RMS + rotary -> bf16 hi/lo [h][t][d]; Q pre-scaled ----------------
__global__ void prep_kernel(const float* __restrict__ qkv) {
    int gwarp = (blockIdx.x * blockDim.x + threadIdx.x) >> 5;
    int lane = threadIdx.x & 31;
    if (gwarp >= T_LEN * HEADS) return;
    int t = gwarp / HEADS;
    int h = gwarp % HEADS;
    const float* base = qkv + (size_t)t * (3 * DIM) + h * HD;

    float q1 = base[lane],            q2 = base[lane + 32];
    float k1 = base[DIM + lane],      k2 = base[DIM + lane + 32];
    float v1 = base[2 * DIM + lane],  v2 = base[2 * DIM + lane + 32];

    float sq = q1 * q1 + q2 * q2;
    float sk = k1 * k1 + k2 * k2;
#pragma unroll
    for (int o = 16; o > 0; o >>= 1) {
        sq += __shfl_xor_sync(0xffffffffu, sq, o);
        sk += __shfl_xor_sync(0xffffffffu, sk, o);
    }
    float rq = rsqrtf(sq * (1.f / 64.f) + RMS_EPS);
    float rk = rsqrtf(sk * (1.f / 64.f) + RMS_EPS);
    q1 *= rq; q2 *= rq;
    k1 *= rk; k2 *= rk;

    float freq = (lane < 16) ? exp2f((float)lane * (-10.0f / 15.0f)) : 0.0f;
    float theta = (float)t * freq;
    float s, c;
    sincosf(theta, &s, &c);

    float qa = (q1 * c + q2 * s) * ATTN_SCALE;
    float qb = (-q1 * s + q2 * c) * ATTN_SCALE;
    float ka = k1 * c + k2 * s;
    float kb = -k1 * s + k2 * c;

    size_t o0 = ((size_t)h * T_LEN + t) * HD + lane;
    size_t o1 = o0 + 32;
#define SPLIT_ST(arrH, arrL, idx, val) do { \
        __nv_bfloat16 _h = __float2bfloat16_rn(val); \
        arrH[idx] = _h; \
        arrL[idx] = __float2bfloat16_rn((val) - __bfloat162float(_h)); \
    } while (0)
    SPLIT_ST(g_Qh, g_Ql, o0, qa); SPLIT_ST(g_Qh, g_Ql, o1, qb);
    SPLIT_ST(g_Kh, g_Kl, o0, ka); SPLIT_ST(g_Kh, g_Kl, o1, kb);
    SPLIT_ST(g_Vh, g_Vl, o0, v1); SPLIT_ST(g_Vh, g_Vl, o1, v2);
#undef SPLIT_ST
}

// ---------------- flash attention: m32n32 warps, DOUBLE-BUFFERED K/V ----------------
// smem dwords: Q 0..8191 | buf0: K 8192..12287, V 12288..16383 | buf1: K 16384.., V 20480..
// one __syncthreads per tile; stores of tile it+1 overlap compute of tile it.
__global__ __launch_bounds__(256, 1)
void flash_mma(float* __restrict__ Y) {
    extern __shared__ uint32_t smw[];
    float* smf = (float*)smw;

    const int h = blockIdx.y;
    const int qb = (gridDim.x - 1) - blockIdx.x;
    const int q0 = qb * 128;
    const int tid = threadIdx.x;
    const int w = tid >> 5;
    const int lane = tid & 31;
    const int gid = lane >> 2;
    const int tig = lane & 3;
    const int wm = w & 3;
    const int wn = w >> 2;
    const int rbase = q0 + wm * 32;

    const uint32_t* gQh = (const uint32_t*)g_Qh + ((size_t)h * T_LEN + q0) * 32;
    const uint32_t* gQl = (const uint32_t*)g_Ql + ((size_t)h * T_LEN + q0) * 32;
    const uint32_t* gKh = (const uint32_t*)g_Kh + (size_t)h * T_LEN * 32;
    const uint32_t* gKl = (const uint32_t*)g_Kl + (size_t)h * T_LEN * 32;
    const uint32_t* gVh = (const uint32_t*)g_Vh + (size_t)h * T_LEN * 32;
    const uint32_t* gVl = (const uint32_t*)g_Vl + (size_t)h * T_LEN * 32;

    // ---- stage Q into A-fragment slots (once) ----
    {
        const int t = tid >> 1;
        const int mt = t >> 4, rr = t & 15;
        const int g8 = rr & 7, wb = rr >> 3;
#pragma unroll
        for (int jj = 0; jj < 2; jj++) {
            int dw0 = (tid & 1) * 16 + jj * 8;
#pragma unroll
            for (int half = 0; half < 2; half++) {
                uint4 qh4 = *(const uint4*)(gQh + (size_t)t * 32 + dw0 + half * 4);
                uint4 ql4 = *(const uint4*)(gQl + (size_t)t * 32 + dw0 + half * 4);
#pragma unroll
                for (int c = 0; c < 4; c++) {
                    int dw = dw0 + half * 4 + c;
                    int s = dw >> 3, tg = dw & 3, hi4 = (dw >> 2) & 1;
                    int addr = ((mt * 4 + s) * 32 + g8 * 4 + tg) * 4 + wb + 2 * hi4;
                    smw[addr] = ((const uint32_t*)&qh4)[c];
                    smw[addr + 4096] = ((const uint32_t*)&ql4)[c];
                }
            }
        }
    }

    const int kt = tid >> 2, kss = tid & 3;
    const int knt = kt >> 3, kg8 = kt & 7;
    const int kdstRel = ((knt * 4 + kss) * 32 + kg8 * 4) * 4;
    const int jp = tid >> 3, dwb = (tid & 7) * 4;
    const int vs = jp >> 3, vqq = jp & 7;
    const int vword = vqq >> 2, vtg = vqq & 3;

    uint4 pk[4], pv[4];

#define LOAD_TILE(k0n) do { \
        const uint32_t* sKh_ = gKh + (size_t)((k0n) + kt) * 32 + kss * 8; \
        const uint32_t* sKl_ = gKl + (size_t)((k0n) + kt) * 32 + kss * 8; \
        pk[0] = *(const uint4*)sKh_;   pk[1] = *(const uint4*)(sKh_ + 4); \
        pk[2] = *(const uint4*)sKl_;   pk[3] = *(const uint4*)(sKl_ + 4); \
        pv[0] = *(const uint4*)(gVh + (size_t)((k0n) + 2 * jp) * 32 + dwb); \
        pv[1] = *(const uint4*)(gVh + (size_t)((k0n) + 2 * jp + 1) * 32 + dwb); \
        pv[2] = *(const uint4*)(gVl + (size_t)((k0n) + 2 * jp) * 32 + dwb); \
        pv[3] = *(const uint4*)(gVl + (size_t)((k0n) + 2 * jp + 1) * 32 + dwb); \
    } while (0)

#define STORE_TILE(bufbase) do { \
        uint32_t* kb_ = smw + (bufbase); \
        uint32_t* vb_ = smw + (bufbase) + 4096; \
        _Pragma("unroll") \
        for (int c = 0; c < 4; c++) { \
            *(uint4*)(kb_ + kdstRel + c * 4) = \
                make_uint4(((uint32_t*)&pk[0])[c], ((uint32_t*)&pk[1])[c], \
                           ((uint32_t*)&pk[2])[c], ((uint32_t*)&pk[3])[c]); \
        } \
        _Pragma("unroll") \
        for (int c = 0; c < 4; c++) { \
            int d0_ = 2 * (dwb + c); \
            int nt8_ = d0_ >> 3, g0_ = d0_ & 7; \
            int slot0_ = (nt8_ * 4 + vs) * 32 + g0_ * 4 + vtg; \
            uint32_t w0_ = ((uint32_t*)&pv[0])[c], w1_ = ((uint32_t*)&pv[1])[c]; \
            uint32_t u0_ = ((uint32_t*)&pv[2])[c], u1_ = ((uint32_t*)&pv[3])[c]; \
            vb_[slot0_ * 4 + vword] = __byte_perm(w0_, w1_, 0x5410); \
            vb_[slot0_ * 4 + vword + 2] = __byte_perm(u0_, u1_, 0x5410); \
            vb_[(slot0_ + 4) * 4 + vword] = __byte_perm(w0_, w1_, 0x7632); \
            vb_[(slot0_ + 4) * 4 + vword + 2] = __byte_perm(u0_, u1_, 0x7632); \
        } \
    } while (0)

    float O[2][8][4];
#pragma unroll
    for (int a = 0; a < 2; a++)
#pragma unroll
        for (int b = 0; b < 8; b++)
#pragma unroll
            for (int c = 0; c < 4; c++) O[a][b][c] = 0.f;
    float lsum[2][2] = {{0.f, 0.f}, {0.f, 0.f}};

    const int ntiles = 2 * qb + 2;

    // prolog: tile0 -> buf0; load tile1 into regs
    LOAD_TILE(0);
    STORE_TILE(8192);
    if (ntiles > 1) LOAD_TILE(64);

    for (int it = 0; it < ntiles; it++) {
        const int k0 = it * 64;
        const int p = it & 1;
        const int cbase = 8192 + p * 8192;       // compute buffer
        __syncthreads();                          // buf p ready; buf p^1 free

        if (it + 1 < ntiles) {
            STORE_TILE(8192 + (p ^ 1) * 8192);   // tile it+1 -> other buffer
            if (it + 2 < ntiles) LOAD_TILE(k0 + 128);
        }

        const int k0c = k0 + wn * 32;
        if (k0c > rbase + 31) continue;

        // ---- S = Q K^T (bf16x3) ----
        float S[2][4][4];
#pragma unroll
        for (int a = 0; a < 2; a++)
#pragma unroll
            for (int b = 0; b < 4; b++)
#pragma unroll
                for (int c = 0; c < 4; c++) S[a][b][c] = 0.f;
#pragma unroll
        for (int s = 0; s < 4; s++) {
            uint4 ah[2], al[2];
#pragma unroll
            for (int mt = 0; mt < 2; mt++) {
                int slot = (((wm * 2 + mt) * 4 + s) * 32 + lane) * 4;
                ah[mt] = *(const uint4*)(smw + slot);
                al[mt] = *(const uint4*)(smw + slot + 4096);
            }
#pragma unroll
            for (int nt = 0; nt < 4; nt++) {
                uint4 kk = *(const uint4*)(smw + cbase +
                                           (((wn * 4 + nt) * 4 + s) * 32 + lane) * 4);
                uint32_t bh[2] = {kk.x, kk.y}, bl[2] = {kk.z, kk.w};
#pragma unroll
                for (int mt = 0; mt < 2; mt++) {
                    mma16816(S[mt][nt], (uint32_t*)&ah[mt], bh);
                    mma16816(S[mt][nt], (uint32_t*)&ah[mt], bl);
                    mma16816(S[mt][nt], (uint32_t*)&al[mt], bh);
                }
            }
        }

        // ---- exp + mask + partial row sums ----
        const bool needmask = (k0c + 31 > rbase);
#pragma unroll
        for (int mt = 0; mt < 2; mt++) {
            const int r0 = rbase + mt * 16 + gid, r1 = r0 + 8;
#pragma unroll
            for (int nt = 0; nt < 4; nt++) {
                int c0 = k0c + nt * 8 + tig * 2;
                float p0 = __expf(S[mt][nt][0]);
                float p1 = __expf(S[mt][nt][1]);
                float p2 = __expf(S[mt][nt][2]);
                float p3 = __expf(S[mt][nt][3]);
                if (needmask) {
                    if (c0 > r0) p0 = 0.f;
                    if (c0 + 1 > r0) p1 = 0.f;
                    if (c0 > r1) p2 = 0.f;
                    if (c0 + 1 > r1) p3 = 0.f;
                }
                lsum[mt][0] += p0 + p1;
                lsum[mt][1] += p2 + p3;
                S[mt][nt][0] = p0; S[mt][nt][1] = p1;
                S[mt][nt][2] = p2; S[mt][nt][3] = p3;
            }
        }

        // ---- O += P V (bf16x3) ----
#pragma unroll
        for (int s2 = 0; s2 < 2; s2++) {
            uint32_t Ph[2][4], Pl[2][4];
#pragma unroll
            for (int mt = 0; mt < 2; mt++) {
                split2(S[mt][2 * s2][0], S[mt][2 * s2][1], Ph[mt][0], Pl[mt][0]);
                split2(S[mt][2 * s2][2], S[mt][2 * s2][3], Ph[mt][1], Pl[mt][1]);
                split2(S[mt][2 * s2 + 1][0], S[mt][2 * s2 + 1][1], Ph[mt][2], Pl[mt][2]);
                split2(S[mt][2 * s2 + 1][2], S[mt][2 * s2 + 1][3], Ph[mt][3], Pl[mt][3]);
            }
#pragma unroll
            for (int nt8 = 0; nt8 < 8; nt8++) {
                uint4 vv = *(const uint4*)(smw + cbase + 4096 +
                                           ((nt8 * 4 + wn * 2 + s2) * 32 + lane) * 4);
                uint32_t bh[2] = {vv.x, vv.y}, bl[2] = {vv.z, vv.w};
#pragma unroll
                for (int mt = 0; mt < 2; mt++) {
                    mma16816(O[mt][nt8], Ph[mt], bh);
                    mma16816(O[mt][nt8], Ph[mt], bl);
                    mma16816(O[mt][nt8], Pl[mt], bh);
                }
            }
        }
    }

#pragma unroll
    for (int mt = 0; mt < 2; mt++)
#pragma unroll
        for (int i = 0; i < 2; i++) {
            lsum[mt][i] += __shfl_xor_sync(0xffffffffu, lsum[mt][i], 1, 4);
            lsum[mt][i] += __shfl_xor_sync(0xffffffffu, lsum[mt][i], 2, 4);
        }

    __syncthreads();
    float* ex = smf + wm * 3072;
    if (wn == 1) {
#pragma unroll
        for (int mt = 0; mt < 2; mt++) {
#pragma unroll
            for (int nt8 = 0; nt8 < 8; nt8++) {
                int col = nt8 * 8 + tig * 2;
                *(float2*)&ex[(mt * 16 + gid) * 66 + col] =
                    make_float2(O[mt][nt8][0], O[mt][nt8][1]);
                *(float2*)&ex[(mt * 16 + gid + 8) * 66 + col] =
                    make_float2(O[mt][nt8][2], O[mt][nt8][3]);
            }
            if (tig == 0) {
                ex[(mt * 16 + gid) * 66 + 64] = lsum[mt][0];
                ex[(mt * 16 + gid + 8) * 66 + 64] = lsum[mt][1];
            }
        }
    }
    __syncthreads();
    if (wn == 0) {
#pragma unroll
        for (int mt = 0; mt < 2; mt++) {
            float lt0 = lsum[mt][0] + ex[(mt * 16 + gid) * 66 + 64];
            float lt1 = lsum[mt][1] + ex[(mt * 16 + gid + 8) * 66 + 64];
            float inv0 = 1.f / lt0, inv1 = 1.f / lt1;
            int r0 = rbase + mt * 16 + gid;
#pragma unroll
            for (int nt8 = 0; nt8 < 8; nt8++) {
                int col = nt8 * 8 + tig * 2;
                float2 e0 = *(float2*)&ex[(mt * 16 + gid) * 66 + col];
                float2 e1 = *(float2*)&ex[(mt * 16 + gid + 8) * 66 + col];
                int yc = h * HD + col;
                *(float2*)&Y[(size_t)r0 * DIM + yc] =
                    make_float2((O[mt][nt8][0] + e0.x) * inv0,
                                (O[mt][nt8][1] + e0.y) * inv0);
                *(float2*)&Y[(size_t)(r0 + 8) * DIM + yc] =
                    make_float2((O[mt][nt8][2] + e1.x) * inv1,
                                (O[mt][nt8][3] + e1.y) * inv1);
            }
        }
    }
#undef LOAD_TILE
#undef STORE_TILE
}

// ---------------- launch: [gemm, prep, flash, proj, nop, nop] ----------------
// capture slot is global launch idx 8 (== 2 mod 6) -> flash_mma gets profiled.
extern "C" void kernel_launch(void* const* d_in, const int* in_sizes, int n_in,
                              void* d_out, int out_size) {
    const float* x = (const float*)d_in[0];
    const float* qkv_w = (const float*)d_in[1];
    const float* c_proj_w = (const float*)d_in[2];
    float* out = (float*)d_out;

    float *qkv, *Yb;
    cudaGetSymbolAddress((void**)&qkv, g_qkv);
    cudaGetSymbolAddress((void**)&Yb, g_Y);

    // 1) qkv = x @ qkv_w^T
    {
        dim3 grid(2304 / 128, T_LEN / 128);
        gemm_mma<<<grid, 256>>>(x, qkv_w, qkv, T_LEN, 2304, DIM);
    }
    // 2) RMS + rotary -> bf16 hi/lo (Q pre-scaled)
    {
        int warps = T_LEN * HEADS;
        int blocks = (warps * 32 + 255) / 256;
        prep_kernel<<<blocks, 256>>>(qkv);
    }
    // 3) flash attention (double-buffered K/V, 96KB smem)
    {
        cudaFuncSetAttribute(flash_mma, cudaFuncAttributeMaxDynamicSharedMemorySize, 98304);
        dim3 grid(T_LEN / 128, HEADS);
        flash_mma<<<grid, 256, 98304>>>(Yb);
    }
    // 4) out = Y @ c_proj_w^T
    {
        dim3 grid(DIM / 128, T_LEN / 128);
        gemm_mma<<<grid, 256>>>(Yb, c_proj_w, out, T_LEN, DIM, DIM);
    }
    // 5,6) pads to keep 6-launch period for ncu capture alignment
    nop_kernel<<<1, 32>>>();
    nop_kernel<<<1, 32>>>();
}